// round 15
// baseline (speedup 1.0000x reference)
#include <cuda_runtime.h>

#define NN 50000
#define E0 800000
#define ET 850000

// ---------------- scratch (static device globals; no allocation) ----------------
__device__ float g_xw1[NN * 64];
__device__ float g_als1[NN * 8];
__device__ float g_ald1[NN * 8];
__device__ float g_h1n[NN * 64];     // elu(agg1/den + b1)
__device__ float g_xw2[NN * 128];
__device__ float g_als2[NN * 8];
__device__ float g_ald2[NN * 8];
__device__ int   g_cnt[NN];
__device__ int   g_off[NN + 1];
__device__ int   g_cur[NN];
__device__ int2  g_csr[ET];          // (src, edge_id) grouped by dst

typedef unsigned long long ull;

// packed dual-FMA: acc.(lo,hi) += a.(lo,hi) * b.(lo,hi)   (two IEEE fp32 FMAs)
__device__ __forceinline__ void ffma2(ull& acc, ull a, ull b) {
    asm("fma.rn.f32x2 %0, %1, %2, %0;" : "+l"(acc) : "l"(a), "l"(b));
}
__device__ __forceinline__ float2 unpk(ull v) {
    float2 r; asm("mov.b64 {%0, %1}, %2;" : "=f"(r.x), "=f"(r.y) : "l"(v)); return r;
}

// ---------------- CSR build ----------------
__global__ __launch_bounds__(256) void k_hist(const int* __restrict__ ei,
                                              int* __restrict__ cnt) {
    int e = blockIdx.x * 256 + threadIdx.x;
    if (e >= ET) return;
    int d = (e < E0) ? __ldg(ei + E0 + e) : (e - E0);
    if ((unsigned)d >= NN) return;
    atomicAdd(cnt + d, 1);
}

__global__ __launch_bounds__(1024) void k_scan(const int* __restrict__ cnt,
                                               int* __restrict__ off,
                                               int* __restrict__ cur) {
    const int PER = (NN + 1023) / 1024;   // 49
    int t = threadIdx.x;
    int base = t * PER;
    int sum = 0;
    for (int i = 0; i < PER; i++) {
        int idx = base + i;
        if (idx < NN) sum += __ldg(cnt + idx);
    }
    int lane = t & 31, wid = t >> 5;
    int v = sum;
#pragma unroll
    for (int o = 1; o < 32; o <<= 1) {
        int n = __shfl_up_sync(0xffffffffu, v, o);
        if (lane >= o) v += n;
    }
    __shared__ int ws[32];
    if (lane == 31) ws[wid] = v;
    __syncthreads();
    if (wid == 0) {
        int w = ws[lane];
#pragma unroll
        for (int o = 1; o < 32; o <<= 1) {
            int n = __shfl_up_sync(0xffffffffu, w, o);
            if (lane >= o) w += n;
        }
        ws[lane] = w;
    }
    __syncthreads();
    int run = v - sum + (wid > 0 ? ws[wid - 1] : 0);   // exclusive prefix
    for (int i = 0; i < PER; i++) {
        int idx = base + i;
        if (idx < NN) {
            off[idx] = run;
            cur[idx] = run;
            run += __ldg(cnt + idx);
        }
    }
    if (t == 1023) off[NN] = run;
}

__global__ __launch_bounds__(256) void k_scatter(const int* __restrict__ ei,
                                                 int* __restrict__ cur,
                                                 int2* __restrict__ csr) {
    int e = blockIdx.x * 256 + threadIdx.x;
    if (e >= ET) return;
    int s, d;
    if (e < E0) { s = __ldg(ei + e); d = __ldg(ei + E0 + e); }
    else        { s = e - E0; d = s; }
    if ((unsigned)s >= NN || (unsigned)d >= NN) return;
    int pos = atomicAdd(cur + d, 1);
    csr[pos] = make_int2(s, e);
}

// ---------------- GEMM1: x[NN,256] @ W1[256,64] -> g_xw1 ----------------
// 128x64 tile, BK=32, 8x4 micro-tile via fma.f32x2 (A duplicated in smem)
__global__ __launch_bounds__(256) void k_gemm1(const float* __restrict__ A,
                                               const float* __restrict__ B,
                                               float* __restrict__ C) {
    __shared__ float2 As2[32][130];   // (v,v) duplicated pairs
    __shared__ float  Bs[32][68];
    int tid = threadIdx.x;
    int tx = tid & 15, ty = tid >> 4;
    int bm = blockIdx.x * 128;
    ull acc[8][2] = {};
    for (int k0 = 0; k0 < 256; k0 += 32) {
        // A tile: 128 rows x 32 k = 1024 float4, duplicated to float2 pairs
#pragma unroll
        for (int i = 0; i < 4; i++) {
            int f = tid + i * 256;
            int row = f >> 3, kq = f & 7;
            int gr = bm + row;
            float4 v = (gr < NN) ? *(const float4*)&A[(size_t)gr * 256 + k0 + kq * 4]
                                 : make_float4(0.f, 0.f, 0.f, 0.f);
            As2[kq * 4 + 0][row] = make_float2(v.x, v.x);
            As2[kq * 4 + 1][row] = make_float2(v.y, v.y);
            As2[kq * 4 + 2][row] = make_float2(v.z, v.z);
            As2[kq * 4 + 3][row] = make_float2(v.w, v.w);
        }
        // B tile: 32 k x 64 n
#pragma unroll
        for (int i = 0; i < 2; i++) {
            int f = tid + i * 256;
            int k = f >> 4, nq = f & 15;
            *(float4*)&Bs[k][nq * 4] = *(const float4*)&B[(size_t)(k0 + k) * 64 + nq * 4];
        }
        __syncthreads();
#pragma unroll
        for (int k = 0; k < 32; k++) {
            ull b01 = *(const ull*)&Bs[k][tx * 4];
            ull b23 = *(const ull*)&Bs[k][tx * 4 + 2];
#pragma unroll
            for (int i = 0; i < 8; i++) {
                ull a = *(const ull*)&As2[k][ty + 16 * i];
                ffma2(acc[i][0], a, b01);
                ffma2(acc[i][1], a, b23);
            }
        }
        __syncthreads();
    }
#pragma unroll
    for (int i = 0; i < 8; i++) {
        int row = bm + ty + 16 * i;
        if (row < NN) {
            float2 c01 = unpk(acc[i][0]);
            float2 c23 = unpk(acc[i][1]);
            *(float4*)&C[(size_t)row * 64 + tx * 4] =
                make_float4(c01.x, c01.y, c23.x, c23.y);
        }
    }
}

// ---------------- GEMM2: h1n[NN,64] @ W2[64,128] -> g_xw2 ----------------
// 128x128 tile, BK=16, 8x8 micro-tile via fma.f32x2
__global__ __launch_bounds__(256) void k_gemm2(const float* __restrict__ A,
                                               const float* __restrict__ B,
                                               float* __restrict__ C) {
    __shared__ float2 As2[16][130];
    __shared__ float  Bs[16][132];
    int tid = threadIdx.x;
    int tx = tid & 15, ty = tid >> 4;
    int bm = blockIdx.x * 128;
    ull acc[8][4] = {};
    for (int k0 = 0; k0 < 64; k0 += 16) {
        // A tile: 128 rows x 16 k = 512 float4
#pragma unroll
        for (int i = 0; i < 2; i++) {
            int f = tid + i * 256;
            int row = f >> 2, kq = f & 3;
            int gr = bm + row;
            float4 v = (gr < NN) ? *(const float4*)&A[(size_t)gr * 64 + k0 + kq * 4]
                                 : make_float4(0.f, 0.f, 0.f, 0.f);
            As2[kq * 4 + 0][row] = make_float2(v.x, v.x);
            As2[kq * 4 + 1][row] = make_float2(v.y, v.y);
            As2[kq * 4 + 2][row] = make_float2(v.z, v.z);
            As2[kq * 4 + 3][row] = make_float2(v.w, v.w);
        }
        // B tile: 16 k x 128 n
#pragma unroll
        for (int i = 0; i < 2; i++) {
            int f = tid + i * 256;
            int k = f >> 5, nq = f & 31;
            *(float4*)&Bs[k][nq * 4] = *(const float4*)&B[(size_t)(k0 + k) * 128 + nq * 4];
        }
        __syncthreads();
#pragma unroll
        for (int k = 0; k < 16; k++) {
            ull b0 = *(const ull*)&Bs[k][tx * 8];
            ull b1 = *(const ull*)&Bs[k][tx * 8 + 2];
            ull b2 = *(const ull*)&Bs[k][tx * 8 + 4];
            ull b3 = *(const ull*)&Bs[k][tx * 8 + 6];
#pragma unroll
            for (int i = 0; i < 8; i++) {
                ull a = *(const ull*)&As2[k][ty + 16 * i];
                ffma2(acc[i][0], a, b0);
                ffma2(acc[i][1], a, b1);
                ffma2(acc[i][2], a, b2);
                ffma2(acc[i][3], a, b3);
            }
        }
        __syncthreads();
    }
#pragma unroll
    for (int i = 0; i < 8; i++) {
        int row = bm + ty + 16 * i;
        if (row < NN) {
            float2 c0 = unpk(acc[i][0]), c1 = unpk(acc[i][1]);
            float2 c2 = unpk(acc[i][2]), c3 = unpk(acc[i][3]);
            *(float4*)&C[(size_t)row * 128 + tx * 8]     = make_float4(c0.x, c0.y, c1.x, c1.y);
            *(float4*)&C[(size_t)row * 128 + tx * 8 + 4] = make_float4(c2.x, c2.y, c3.x, c3.y);
        }
    }
}

// ---------------- attention logits ----------------
template <int D>
__global__ __launch_bounds__(256) void k_attn(const float* __restrict__ xw,
                                              const float* __restrict__ as_,
                                              const float* __restrict__ ad_,
                                              float* __restrict__ als,
                                              float* __restrict__ ald) {
    int t = blockIdx.x * 256 + threadIdx.x;
    if (t >= NN * 8) return;
    int n = t >> 3, h = t & 7;
    const float* row = xw + (size_t)n * 8 * D + h * D;
    float s = 0.f, d = 0.f;
#pragma unroll
    for (int i = 0; i < D; i++) {
        float v = __ldg(row + i);
        s += v * __ldg(as_ + h * D + i);
        d += v * __ldg(ad_ + h * D + i);
    }
    als[t] = s;
    ald[t] = d;
}

// ---------------- layer-1 aggregation: warp per dst node ----------------
__global__ __launch_bounds__(256) void k_agg1(const int* __restrict__ off,
                                              const int2* __restrict__ csr,
                                              const float* __restrict__ als,
                                              const float* __restrict__ ald,
                                              const float* __restrict__ xw,
                                              const float* __restrict__ b1,
                                              float* __restrict__ h1n,
                                              float* __restrict__ alpha_out) {
    int node = blockIdx.x * 8 + (threadIdx.x >> 5);
    if (node >= NN) return;
    int lane = threadIdx.x & 31;
    int h = lane >> 2;
    float aldv = __ldg(ald + node * 8 + h);
    int beg = __ldg(off + node), end = __ldg(off + node + 1);
    float acc0 = 0.f, acc1 = 0.f, den = 0.f;
    for (int i = beg; i < end; i++) {
        int2 se = __ldg(csr + i);
        float v = __ldg(als + se.x * 8 + h) + aldv;
        v = v > 0.f ? v : 0.2f * v;            // leaky_relu
        float ee = __expf(v);
        den += ee;
        float2 m = *(const float2*)(xw + (size_t)se.x * 64 + lane * 2);
        acc0 += ee * m.x;
        acc1 += ee * m.y;
    }
    float inv = 1.f / (den + 1e-16f);
    int c = lane * 2;
    float v0 = acc0 * inv + __ldg(b1 + c);
    float v1 = acc1 * inv + __ldg(b1 + c + 1);
    v0 = v0 > 0.f ? v0 : (__expf(v0) - 1.f);   // ELU
    v1 = v1 > 0.f ? v1 : (__expf(v1) - 1.f);
    *(float2*)(h1n + (size_t)node * 64 + c) = make_float2(v0, v1);

    if (alpha_out) {
        int ha = lane & 7;
        float invh = __shfl_sync(0xffffffffu, inv, ha * 4);
        float aldva = __ldg(ald + node * 8 + ha);
        for (int i0 = beg; i0 < end; i0 += 4) {
            int i = i0 + (lane >> 3);
            if (i < end) {
                int2 se = __ldg(csr + i);
                float v = __ldg(als + se.x * 8 + ha) + aldva;
                v = v > 0.f ? v : 0.2f * v;
                alpha_out[(size_t)se.y * 8 + ha] = __expf(v) * invh;
            }
        }
    }
}

// ---------------- layer-2 aggregation + bias + log_softmax ----------------
__global__ __launch_bounds__(256) void k_agg2(const int* __restrict__ off,
                                              const int2* __restrict__ csr,
                                              const float* __restrict__ als,
                                              const float* __restrict__ ald,
                                              const float* __restrict__ xw,
                                              const float* __restrict__ b2,
                                              float* __restrict__ out) {
    int node = blockIdx.x * 8 + (threadIdx.x >> 5);
    if (node >= NN) return;
    int lane = threadIdx.x & 31;
    int h = lane >> 2;
    float aldv = __ldg(ald + node * 8 + h);
    int beg = __ldg(off + node), end = __ldg(off + node + 1);
    float a0 = 0.f, a1 = 0.f, a2 = 0.f, a3 = 0.f, den = 0.f;
    for (int i = beg; i < end; i++) {
        int2 se = __ldg(csr + i);
        float v = __ldg(als + se.x * 8 + h) + aldv;
        v = v > 0.f ? v : 0.2f * v;
        float ee = __expf(v);
        den += ee;
        float4 m = *(const float4*)(xw + (size_t)se.x * 128 + lane * 4);
        a0 += ee * m.x;
        a1 += ee * m.y;
        a2 += ee * m.z;
        a3 += ee * m.w;
    }
    float inv = 1.f / (den + 1e-16f);
    int c = lane * 4;
    float4 b = *(const float4*)(b2 + c);
    float v0 = a0 * inv + b.x, v1 = a1 * inv + b.y;
    float v2 = a2 * inv + b.z, v3 = a3 * inv + b.w;
    float mx = fmaxf(fmaxf(v0, v1), fmaxf(v2, v3));
#pragma unroll
    for (int o = 16; o > 0; o >>= 1) mx = fmaxf(mx, __shfl_xor_sync(0xffffffffu, mx, o));
    float se_ = __expf(v0 - mx) + __expf(v1 - mx) + __expf(v2 - mx) + __expf(v3 - mx);
#pragma unroll
    for (int o = 16; o > 0; o >>= 1) se_ += __shfl_xor_sync(0xffffffffu, se_, o);
    float ls = mx + __logf(se_);
    *(float4*)(out + (size_t)node * 128 + c) =
        make_float4(v0 - ls, v1 - ls, v2 - ls, v3 - ls);
}

// ---------------- launch ----------------
extern "C" void kernel_launch(void* const* d_in, const int* in_sizes, int n_in,
                              void* d_out, int out_size) {
    const float* x   = (const float*)d_in[0];
    const int*   ei  = (const int*)d_in[1];
    const float* W1  = (const float*)d_in[2];
    const float* a1s = (const float*)d_in[3];
    const float* a1d = (const float*)d_in[4];
    const float* b1  = (const float*)d_in[5];
    const float* W2  = (const float*)d_in[6];
    const float* a2s = (const float*)d_in[7];
    const float* a2d = (const float*)d_in[8];
    const float* b2  = (const float*)d_in[9];

    float* out = (float*)d_out;

    float *xw1, *als1, *ald1, *h1n, *xw2, *als2, *ald2;
    int *cnt, *off, *cur;
    int2 *csr;
    cudaGetSymbolAddress((void**)&xw1,  g_xw1);
    cudaGetSymbolAddress((void**)&als1, g_als1);
    cudaGetSymbolAddress((void**)&ald1, g_ald1);
    cudaGetSymbolAddress((void**)&h1n,  g_h1n);
    cudaGetSymbolAddress((void**)&xw2,  g_xw2);
    cudaGetSymbolAddress((void**)&als2, g_als2);
    cudaGetSymbolAddress((void**)&ald2, g_ald2);
    cudaGetSymbolAddress((void**)&cnt,  g_cnt);
    cudaGetSymbolAddress((void**)&off,  g_off);
    cudaGetSymbolAddress((void**)&cur,  g_cur);
    cudaGetSymbolAddress((void**)&csr,  g_csr);

    cudaMemsetAsync(cnt, 0, (size_t)NN * 4);

    const int gemm_grid = (NN + 127) / 128;
    const int attn_grid = (NN * 8 + 255) / 256;
    const int edge_grid = (ET + 255) / 256;
    const int agg_grid  = (NN + 7) / 8;

    bool want_alpha = (size_t)out_size >= (size_t)NN * 128 + (size_t)ET * 8;
    bool want_logp  = out_size >= NN * 128;

    // CSR build (by destination)
    k_hist<<<edge_grid, 256>>>(ei, cnt);
    k_scan<<<1, 1024>>>(cnt, off, cur);
    k_scatter<<<edge_grid, 256>>>(ei, cur, csr);

    // Layer 1
    k_gemm1<<<gemm_grid, 256>>>(x, W1, xw1);
    k_attn<8><<<attn_grid, 256>>>(xw1, a1s, a1d, als1, ald1);
    k_agg1<<<agg_grid, 256>>>(off, csr, als1, ald1, xw1, b1, h1n,
                              want_alpha ? out + (size_t)NN * 128 : nullptr);

    // Layer 2 (fully fused epilogue: normalize + bias + log_softmax)
    k_gemm2<<<gemm_grid, 256>>>(h1n, W2, xw2);
    k_attn<16><<<attn_grid, 256>>>(xw2, a2s, a2d, als2, ald2);
    if (want_logp) {
        k_agg2<<<agg_grid, 256>>>(off, csr, als2, ald2, xw2, b2, out);
    }
}

// round 16
// speedup vs baseline: 1.1320x; 1.1320x over previous
#include <cuda_runtime.h>

#define NN 50000
#define E0 800000
#define ET 850000

// ---------------- scratch (static device globals; no allocation) ----------------
__device__ float g_xw1[NN * 64];
__device__ float g_als1[NN * 8];
__device__ float g_ald1[NN * 8];
__device__ float g_h1n[NN * 64];     // elu(agg1/den + b1)
__device__ float g_xw2[NN * 128];
__device__ float g_als2[NN * 8];
__device__ float g_ald2[NN * 8];
__device__ int   g_cnt[NN];
__device__ int   g_off[NN + 1];
__device__ int   g_cur[NN];
__device__ int2  g_csr[ET];          // (src, edge_id) grouped by dst

// ---------------- CSR build ----------------
__global__ __launch_bounds__(256) void k_hist(const int* __restrict__ ei,
                                              int* __restrict__ cnt) {
    int e = blockIdx.x * 256 + threadIdx.x;
    if (e >= ET) return;
    int d = (e < E0) ? __ldg(ei + E0 + e) : (e - E0);
    if ((unsigned)d >= NN) return;
    atomicAdd(cnt + d, 1);
}

__global__ __launch_bounds__(1024) void k_scan(const int* __restrict__ cnt,
                                               int* __restrict__ off,
                                               int* __restrict__ cur) {
    const int PER = (NN + 1023) / 1024;   // 49
    int t = threadIdx.x;
    int base = t * PER;
    int sum = 0;
    for (int i = 0; i < PER; i++) {
        int idx = base + i;
        if (idx < NN) sum += __ldg(cnt + idx);
    }
    int lane = t & 31, wid = t >> 5;
    int v = sum;
#pragma unroll
    for (int o = 1; o < 32; o <<= 1) {
        int n = __shfl_up_sync(0xffffffffu, v, o);
        if (lane >= o) v += n;
    }
    __shared__ int ws[32];
    if (lane == 31) ws[wid] = v;
    __syncthreads();
    if (wid == 0) {
        int w = ws[lane];
#pragma unroll
        for (int o = 1; o < 32; o <<= 1) {
            int n = __shfl_up_sync(0xffffffffu, w, o);
            if (lane >= o) w += n;
        }
        ws[lane] = w;
    }
    __syncthreads();
    int run = v - sum + (wid > 0 ? ws[wid - 1] : 0);   // exclusive prefix
    for (int i = 0; i < PER; i++) {
        int idx = base + i;
        if (idx < NN) {
            off[idx] = run;
            cur[idx] = run;
            run += __ldg(cnt + idx);
        }
    }
    if (t == 1023) off[NN] = run;
}

__global__ __launch_bounds__(256) void k_scatter(const int* __restrict__ ei,
                                                 int* __restrict__ cur,
                                                 int2* __restrict__ csr) {
    int e = blockIdx.x * 256 + threadIdx.x;
    if (e >= ET) return;
    int s, d;
    if (e < E0) { s = __ldg(ei + e); d = __ldg(ei + E0 + e); }
    else        { s = e - E0; d = s; }
    if ((unsigned)s >= NN || (unsigned)d >= NN) return;
    int pos = atomicAdd(cur + d, 1);
    csr[pos] = make_int2(s, e);
}

// ---------------- GEMM1: x[NN,256] @ W1[256,64] -> g_xw1, + attn logits fused ----------------
// 128x64 block tile, BK=32, 8x4 micro-tile, 256 threads (R12 proven config)
// Epilogue: head h = tx>>1 lives in tx pair (2h,2h+1) = adjacent lanes -> shfl_xor(1)
__global__ __launch_bounds__(256) void k_gemm1(const float* __restrict__ A,
                                               const float* __restrict__ B,
                                               const float* __restrict__ as_,
                                               const float* __restrict__ ad_,
                                               float* __restrict__ C,
                                               float* __restrict__ als,
                                               float* __restrict__ ald) {
    __shared__ float As[32][132];
    __shared__ float Bs[32][68];
    int tid = threadIdx.x;
    int tx = tid & 15, ty = tid >> 4;
    int bm = blockIdx.x * 128;
    float acc[8][4] = {};
    for (int k0 = 0; k0 < 256; k0 += 32) {
#pragma unroll
        for (int i = 0; i < 4; i++) {
            int f = tid + i * 256;
            int row = f >> 3, kq = f & 7;
            int gr = bm + row;
            float4 v = (gr < NN) ? *(const float4*)&A[(size_t)gr * 256 + k0 + kq * 4]
                                 : make_float4(0.f, 0.f, 0.f, 0.f);
            As[kq * 4 + 0][row] = v.x;
            As[kq * 4 + 1][row] = v.y;
            As[kq * 4 + 2][row] = v.z;
            As[kq * 4 + 3][row] = v.w;
        }
#pragma unroll
        for (int i = 0; i < 2; i++) {
            int f = tid + i * 256;
            int k = f >> 4, nq = f & 15;
            *(float4*)&Bs[k][nq * 4] = *(const float4*)&B[(size_t)(k0 + k) * 64 + nq * 4];
        }
        __syncthreads();
#pragma unroll
        for (int k = 0; k < 32; k++) {
            float4 a0 = *(const float4*)&As[k][ty * 8];
            float4 a1 = *(const float4*)&As[k][ty * 8 + 4];
            float4 b0 = *(const float4*)&Bs[k][tx * 4];
            float av[8] = {a0.x, a0.y, a0.z, a0.w, a1.x, a1.y, a1.z, a1.w};
            float bv[4] = {b0.x, b0.y, b0.z, b0.w};
#pragma unroll
            for (int i = 0; i < 8; i++)
#pragma unroll
                for (int j = 0; j < 4; j++) acc[i][j] += av[i] * bv[j];
        }
        __syncthreads();
    }
    // attn coeffs for this thread's 4 columns: head h = tx>>1, offs = (tx&1)*4 + j
    int h = tx >> 1;
    float4 ws = *(const float4*)&as_[h * 8 + (tx & 1) * 4];
    float4 wd = *(const float4*)&ad_[h * 8 + (tx & 1) * 4];
#pragma unroll
    for (int i = 0; i < 8; i++) {
        int row = bm + ty * 8 + i;
        if (row < NN) {
            *(float4*)&C[(size_t)row * 64 + tx * 4] =
                make_float4(acc[i][0], acc[i][1], acc[i][2], acc[i][3]);
            float sp = acc[i][0] * ws.x + acc[i][1] * ws.y + acc[i][2] * ws.z + acc[i][3] * ws.w;
            float dp = acc[i][0] * wd.x + acc[i][1] * wd.y + acc[i][2] * wd.z + acc[i][3] * wd.w;
            sp += __shfl_xor_sync(0xffffffffu, sp, 1);
            dp += __shfl_xor_sync(0xffffffffu, dp, 1);
            if ((tx & 1) == 0) {
                als[row * 8 + h] = sp;
                ald[row * 8 + h] = dp;
            }
        }
    }
}

// ---------------- GEMM2: h1n[NN,64] @ W2[64,128] -> g_xw2, + attn logits fused ----------------
// 128x128 block tile, BK=16, 8x8 micro-tile (R12 proven config)
__global__ __launch_bounds__(256) void k_gemm2(const float* __restrict__ A,
                                               const float* __restrict__ B,
                                               const float* __restrict__ as_,
                                               const float* __restrict__ ad_,
                                               float* __restrict__ C,
                                               float* __restrict__ als,
                                               float* __restrict__ ald) {
    __shared__ float As[16][132];
    __shared__ float Bs[16][132];
    int tid = threadIdx.x;
    int tx = tid & 15, ty = tid >> 4;
    int bm = blockIdx.x * 128;
    float acc[8][8] = {};
    for (int k0 = 0; k0 < 64; k0 += 16) {
#pragma unroll
        for (int i = 0; i < 2; i++) {
            int f = tid + i * 256;
            int row = f >> 2, kq = f & 3;
            int gr = bm + row;
            float4 v = (gr < NN) ? *(const float4*)&A[(size_t)gr * 64 + k0 + kq * 4]
                                 : make_float4(0.f, 0.f, 0.f, 0.f);
            As[kq * 4 + 0][row] = v.x;
            As[kq * 4 + 1][row] = v.y;
            As[kq * 4 + 2][row] = v.z;
            As[kq * 4 + 3][row] = v.w;
        }
#pragma unroll
        for (int i = 0; i < 2; i++) {
            int f = tid + i * 256;
            int k = f >> 5, nq = f & 31;
            *(float4*)&Bs[k][nq * 4] = *(const float4*)&B[(size_t)(k0 + k) * 128 + nq * 4];
        }
        __syncthreads();
#pragma unroll
        for (int k = 0; k < 16; k++) {
            float4 a0 = *(const float4*)&As[k][ty * 8];
            float4 a1 = *(const float4*)&As[k][ty * 8 + 4];
            float4 b0 = *(const float4*)&Bs[k][tx * 8];
            float4 b1 = *(const float4*)&Bs[k][tx * 8 + 4];
            float av[8] = {a0.x, a0.y, a0.z, a0.w, a1.x, a1.y, a1.z, a1.w};
            float bv[8] = {b0.x, b0.y, b0.z, b0.w, b1.x, b1.y, b1.z, b1.w};
#pragma unroll
            for (int i = 0; i < 8; i++)
#pragma unroll
                for (int j = 0; j < 8; j++) acc[i][j] += av[i] * bv[j];
        }
        __syncthreads();
    }
    // attn coeffs: head h = tx>>1 (16 dims), this thread owns offs (tx&1)*8 + 0..7
    int h = tx >> 1;
    float wsv[8], wdv[8];
#pragma unroll
    for (int j = 0; j < 8; j++) {
        wsv[j] = __ldg(as_ + h * 16 + (tx & 1) * 8 + j);
        wdv[j] = __ldg(ad_ + h * 16 + (tx & 1) * 8 + j);
    }
#pragma unroll
    for (int i = 0; i < 8; i++) {
        int row = bm + ty * 8 + i;
        if (row < NN) {
            *(float4*)&C[(size_t)row * 128 + tx * 8]     = make_float4(acc[i][0], acc[i][1], acc[i][2], acc[i][3]);
            *(float4*)&C[(size_t)row * 128 + tx * 8 + 4] = make_float4(acc[i][4], acc[i][5], acc[i][6], acc[i][7]);
            float sp = 0.f, dp = 0.f;
#pragma unroll
            for (int j = 0; j < 8; j++) {
                sp += acc[i][j] * wsv[j];
                dp += acc[i][j] * wdv[j];
            }
            sp += __shfl_xor_sync(0xffffffffu, sp, 1);
            dp += __shfl_xor_sync(0xffffffffu, dp, 1);
            if ((tx & 1) == 0) {
                als[row * 8 + h] = sp;
                ald[row * 8 + h] = dp;
            }
        }
    }
}

// ---------------- layer-1 aggregation: warp per dst node ----------------
__global__ __launch_bounds__(256) void k_agg1(const int* __restrict__ off,
                                              const int2* __restrict__ csr,
                                              const float* __restrict__ als,
                                              const float* __restrict__ ald,
                                              const float* __restrict__ xw,
                                              const float* __restrict__ b1,
                                              float* __restrict__ h1n,
                                              float* __restrict__ alpha_out) {
    int node = blockIdx.x * 8 + (threadIdx.x >> 5);
    if (node >= NN) return;
    int lane = threadIdx.x & 31;
    int h = lane >> 2;
    float aldv = __ldg(ald + node * 8 + h);
    int beg = __ldg(off + node), end = __ldg(off + node + 1);
    float acc0 = 0.f, acc1 = 0.f, den = 0.f;
    for (int i = beg; i < end; i++) {
        int2 se = __ldg(csr + i);
        float v = __ldg(als + se.x * 8 + h) + aldv;
        v = v > 0.f ? v : 0.2f * v;            // leaky_relu
        float ee = __expf(v);
        den += ee;
        float2 m = *(const float2*)(xw + (size_t)se.x * 64 + lane * 2);
        acc0 += ee * m.x;
        acc1 += ee * m.y;
    }
    float inv = 1.f / (den + 1e-16f);
    int c = lane * 2;
    float v0 = acc0 * inv + __ldg(b1 + c);
    float v1 = acc1 * inv + __ldg(b1 + c + 1);
    v0 = v0 > 0.f ? v0 : (__expf(v0) - 1.f);   // ELU
    v1 = v1 > 0.f ? v1 : (__expf(v1) - 1.f);
    *(float2*)(h1n + (size_t)node * 64 + c) = make_float2(v0, v1);

    if (alpha_out) {
        int ha = lane & 7;
        float invh = __shfl_sync(0xffffffffu, inv, ha * 4);
        float aldva = __ldg(ald + node * 8 + ha);
        for (int i0 = beg; i0 < end; i0 += 4) {
            int i = i0 + (lane >> 3);
            if (i < end) {
                int2 se = __ldg(csr + i);
                float v = __ldg(als + se.x * 8 + ha) + aldva;
                v = v > 0.f ? v : 0.2f * v;
                alpha_out[(size_t)se.y * 8 + ha] = __expf(v) * invh;
            }
        }
    }
}

// ---------------- layer-2 aggregation + bias + log_softmax ----------------
__global__ __launch_bounds__(256) void k_agg2(const int* __restrict__ off,
                                              const int2* __restrict__ csr,
                                              const float* __restrict__ als,
                                              const float* __restrict__ ald,
                                              const float* __restrict__ xw,
                                              const float* __restrict__ b2,
                                              float* __restrict__ out) {
    int node = blockIdx.x * 8 + (threadIdx.x >> 5);
    if (node >= NN) return;
    int lane = threadIdx.x & 31;
    int h = lane >> 2;
    float aldv = __ldg(ald + node * 8 + h);
    int beg = __ldg(off + node), end = __ldg(off + node + 1);
    float a0 = 0.f, a1 = 0.f, a2 = 0.f, a3 = 0.f, den = 0.f;
    for (int i = beg; i < end; i++) {
        int2 se = __ldg(csr + i);
        float v = __ldg(als + se.x * 8 + h) + aldv;
        v = v > 0.f ? v : 0.2f * v;
        float ee = __expf(v);
        den += ee;
        float4 m = *(const float4*)(xw + (size_t)se.x * 128 + lane * 4);
        a0 += ee * m.x;
        a1 += ee * m.y;
        a2 += ee * m.z;
        a3 += ee * m.w;
    }
    float inv = 1.f / (den + 1e-16f);
    int c = lane * 4;
    float4 b = *(const float4*)(b2 + c);
    float v0 = a0 * inv + b.x, v1 = a1 * inv + b.y;
    float v2 = a2 * inv + b.z, v3 = a3 * inv + b.w;
    float mx = fmaxf(fmaxf(v0, v1), fmaxf(v2, v3));
#pragma unroll
    for (int o = 16; o > 0; o >>= 1) mx = fmaxf(mx, __shfl_xor_sync(0xffffffffu, mx, o));
    float se_ = __expf(v0 - mx) + __expf(v1 - mx) + __expf(v2 - mx) + __expf(v3 - mx);
#pragma unroll
    for (int o = 16; o > 0; o >>= 1) se_ += __shfl_xor_sync(0xffffffffu, se_, o);
    float ls = mx + __logf(se_);
    *(float4*)(out + (size_t)node * 128 + c) =
        make_float4(v0 - ls, v1 - ls, v2 - ls, v3 - ls);
}

// ---------------- launch ----------------
extern "C" void kernel_launch(void* const* d_in, const int* in_sizes, int n_in,
                              void* d_out, int out_size) {
    const float* x   = (const float*)d_in[0];
    const int*   ei  = (const int*)d_in[1];
    const float* W1  = (const float*)d_in[2];
    const float* a1s = (const float*)d_in[3];
    const float* a1d = (const float*)d_in[4];
    const float* b1  = (const float*)d_in[5];
    const float* W2  = (const float*)d_in[6];
    const float* a2s = (const float*)d_in[7];
    const float* a2d = (const float*)d_in[8];
    const float* b2  = (const float*)d_in[9];

    float* out = (float*)d_out;

    float *xw1, *als1, *ald1, *h1n, *xw2, *als2, *ald2;
    int *cnt, *off, *cur;
    int2 *csr;
    cudaGetSymbolAddress((void**)&xw1,  g_xw1);
    cudaGetSymbolAddress((void**)&als1, g_als1);
    cudaGetSymbolAddress((void**)&ald1, g_ald1);
    cudaGetSymbolAddress((void**)&h1n,  g_h1n);
    cudaGetSymbolAddress((void**)&xw2,  g_xw2);
    cudaGetSymbolAddress((void**)&als2, g_als2);
    cudaGetSymbolAddress((void**)&ald2, g_ald2);
    cudaGetSymbolAddress((void**)&cnt,  g_cnt);
    cudaGetSymbolAddress((void**)&off,  g_off);
    cudaGetSymbolAddress((void**)&cur,  g_cur);
    cudaGetSymbolAddress((void**)&csr,  g_csr);

    cudaMemsetAsync(cnt, 0, (size_t)NN * 4);

    const int gemm_grid = (NN + 127) / 128;
    const int edge_grid = (ET + 255) / 256;
    const int agg_grid  = (NN + 7) / 8;

    bool want_alpha = (size_t)out_size >= (size_t)NN * 128 + (size_t)ET * 8;
    bool want_logp  = out_size >= NN * 128;

    // CSR build (by destination)
    k_hist<<<edge_grid, 256>>>(ei, cnt);
    k_scan<<<1, 1024>>>(cnt, off, cur);
    k_scatter<<<edge_grid, 256>>>(ei, cur, csr);

    // Layer 1 (attn logits fused into GEMM epilogue)
    k_gemm1<<<gemm_grid, 256>>>(x, W1, a1s, a1d, xw1, als1, ald1);
    k_agg1<<<agg_grid, 256>>>(off, csr, als1, ald1, xw1, b1, h1n,
                              want_alpha ? out + (size_t)NN * 128 : nullptr);

    // Layer 2 (attn fused; epilogue of agg2: normalize + bias + log_softmax)
    k_gemm2<<<gemm_grid, 256>>>(h1n, W2, a2s, a2d, xw2, als2, ald2);
    if (want_logp) {
        k_agg2<<<agg_grid, 256>>>(off, csr, als2, ald2, xw2, b2, out);
    }
}